// round 13
// baseline (speedup 1.0000x reference)
#include <cuda_runtime.h>
#include <cuda_fp16.h>
#include <cstddef>

#define DIM 128
#define MAX_GROUPS 50000
#define MAX_USERS  200000
#define MAX_NNZ    2000000

#define H_SCALE   0.0009765625f   // 2^-10 (exact)
#define H_UNSCALE 1024.0f         // 2^10  (exact)

// ---------------------------------------------------------------------------
// Scratch (device globals; no allocation allowed)
// ---------------------------------------------------------------------------
__device__ float g_node_msg[(size_t)MAX_GROUPS * DIM];
__device__ __half g_userh[(size_t)MAX_USERS * DIM];          // fp16 user operand (scaled 2^-10)
__device__ __half g_msgh[3][(size_t)MAX_GROUPS * DIM];       // fp16 msg slots (scaled 2^-10)

__device__ int  g_cnt[MAX_GROUPS + MAX_USERS];   // cntA | cntB (zeroed by conv kernel)
__device__ int  g_ptrA[MAX_GROUPS + 1];
__device__ int  g_workA[MAX_GROUPS];
__device__ int2 g_ivA[MAX_NNZ];          // CSR by group row: (user_col, val)

__device__ int  g_ptrB[MAX_USERS + 1];
__device__ int  g_workB[MAX_USERS];
__device__ int2 g_ivB[MAX_NNZ];          // CSC by user col: (group_row, val)

// decoupled-lookback state: [0,256) = segment A, [256,512) = segment B
// packed word: (status << 32) | value ; status 0=invalid 1=aggregate 2=prefix
__device__ unsigned long long g_scanflags[512];

// ---------------------------------------------------------------------------
// f32x2 packed-math helpers (Blackwell FFMA2 via PTX)
// ---------------------------------------------------------------------------
__device__ __forceinline__ unsigned long long pack2(float lo, float hi)
{
    unsigned long long r;
    asm("mov.b64 %0, {%1, %2};" : "=l"(r) : "f"(lo), "f"(hi));
    return r;
}
__device__ __forceinline__ void ffma2(unsigned long long& d,
                                      unsigned long long a, unsigned long long b)
{
    asm("fma.rn.f32x2 %0, %1, %2, %0;" : "+l"(d) : "l"(a), "l"(b));
}
__device__ __forceinline__ float2 unpack2(unsigned long long v)
{
    float2 r;
    asm("mov.b64 {%0, %1}, %2;" : "=f"(r.x), "=f"(r.y) : "l"(v));
    return r;
}

// unpack 4 halfs -> float4
__device__ __forceinline__ float4 unpack_h4(unsigned lo, unsigned hi)
{
    __half2 h0 = *reinterpret_cast<__half2*>(&lo);
    __half2 h1 = *reinterpret_cast<__half2*>(&hi);
    float2 a = __half22float2(h0);
    float2 b = __half22float2(h1);
    return make_float4(a.x, a.y, b.x, b.y);
}
// pack float4 -> 4 halfs (uint2)
__device__ __forceinline__ uint2 pack_h4(float4 v)
{
    __half2 h0 = __floats2half2_rn(v.x, v.y);
    __half2 h1 = __floats2half2_rn(v.z, v.w);
    uint2 r;
    r.x = *reinterpret_cast<unsigned*>(&h0);
    r.y = *reinterpret_cast<unsigned*>(&h1);
    return r;
}

// ---------------------------------------------------------------------------
// fp32 -> scaled fp16 for BOTH embeddings; ALSO zeroes histogram counters and
// scan flags (replaces the cudaMemsetAsync node).
__global__ void f32_to_f16_dual_kernel(const float4* __restrict__ a, uint2* __restrict__ oa, int n4a,
                                       const float4* __restrict__ b, uint2* __restrict__ ob, int n4b,
                                       int n_cnt)
{
    int i = blockIdx.x * blockDim.x + threadIdx.x;
    if (i < n_cnt) g_cnt[i] = 0;
    if (i < 512)   g_scanflags[i] = 0ull;
    if (i < n4a) {
        float4 v = a[i];
        v.x *= H_SCALE; v.y *= H_SCALE; v.z *= H_SCALE; v.w *= H_SCALE;
        oa[i] = pack_h4(v);
    } else if (i < n4a + n4b) {
        int j = i - n4a;
        float4 v = b[j];
        v.x *= H_SCALE; v.y *= H_SCALE; v.z *= H_SCALE; v.w *= H_SCALE;
        ob[j] = pack_h4(v);
    }
}

// ---------------------------------------------------------------------------
// CSR build: histogram -> single-pass decoupled-lookback scan -> scatter
// ---------------------------------------------------------------------------
__global__ void hist_kernel(const int* __restrict__ rows, const int* __restrict__ cols,
                            int* __restrict__ cntA, int* __restrict__ cntB, int nnz)
{
    int i = blockIdx.x * blockDim.x + threadIdx.x;
    if (i < nnz) {
        atomicAdd(cntA + rows[i], 1);
        atomicAdd(cntB + cols[i], 1);
    }
}

// One launch scans both segments. Per 1024-block: smem inclusive scan, then
// decoupled lookback over earlier blocks of the same segment.
// out (= ptr+1) gets the inclusive scan; work gets the exclusive start.
__global__ __launch_bounds__(1024)
void scan_lookback_kernel(const int* __restrict__ cntA, int* __restrict__ outA,
                          int* __restrict__ workA, int* __restrict__ ptrA0,
                          int nA, int nbA,
                          const int* __restrict__ cntB, int* __restrict__ outB,
                          int* __restrict__ workB, int* __restrict__ ptrB0,
                          int nB)
{
    __shared__ int sm[1024];
    __shared__ int s_prefix;

    const int* cnt; int* out; int* work; int* p0; int n; int bid;
    unsigned long long* flags;
    if ((int)blockIdx.x < nbA) {
        cnt = cntA; out = outA; work = workA; p0 = ptrA0; n = nA;
        bid = blockIdx.x; flags = g_scanflags;
    } else {
        cnt = cntB; out = outB; work = workB; p0 = ptrB0; n = nB;
        bid = blockIdx.x - nbA; flags = g_scanflags + 256;
    }

    int i = bid * 1024 + threadIdx.x;
    int v = (i < n) ? cnt[i] : 0;
    sm[threadIdx.x] = v;
    __syncthreads();
    for (int off = 1; off < 1024; off <<= 1) {
        int t = (threadIdx.x >= off) ? sm[threadIdx.x - off] : 0;
        __syncthreads();
        sm[threadIdx.x] += t;
        __syncthreads();
    }

    if (threadIdx.x == 0) {
        int agg = sm[1023];
        if (bid == 0) {
            atomicExch(&flags[0], (2ull << 32) | (unsigned)agg);
            s_prefix = 0;
        } else {
            atomicExch(&flags[bid], (1ull << 32) | (unsigned)agg);
            int running = 0;
            int j = bid - 1;
            while (j >= 0) {
                unsigned long long f = atomicAdd(&flags[j], 0ull);
                unsigned st = (unsigned)(f >> 32);
                if (st == 0) continue;            // spin: predecessor not ready
                running += (int)(unsigned)f;
                if (st == 2) break;               // hit a full prefix
                j--;
            }
            atomicExch(&flags[bid], (2ull << 32) | (unsigned)(running + agg));
            s_prefix = running;
        }
        if (bid == 0) *p0 = 0;
    }
    __syncthreads();

    if (i < n) {
        int incl = sm[threadIdx.x] + s_prefix;
        out[i] = incl;
        work[i] = incl - v;
    }
}

__global__ void scatter_kernel(const int* __restrict__ rows, const int* __restrict__ cols,
                               const float* __restrict__ vals,
                               int* __restrict__ workA, int2* __restrict__ ivA,
                               int* __restrict__ workB, int2* __restrict__ ivB, int nnz)
{
    int i = blockIdx.x * blockDim.x + threadIdx.x;
    if (i >= nnz) return;
    int r = rows[i], c = cols[i];
    int v = __float_as_int(vals[i]);
    int pa = atomicAdd(workA + r, 1);
    ivA[pa] = make_int2(c, v);
    int pb = atomicAdd(workB + c, 1);
    ivB[pb] = make_int2(r, v);
}

// ---------------------------------------------------------------------------
// CSR SpMM, HALF-WARP per row (16 lanes x LDG.128 = 256B fp16 row):
// unroll-4 main loop + serial tail (known-good R9/R11 form).
//   if (out_h)   out_h[row]   = acc_raw    (fp16, scaled domain)
//   if (out_f)   out_f[row]   = acc_raw * 1024
//   if (sum_out) sum_out[row] = sum_base[row] + acc_raw * 1024
// ---------------------------------------------------------------------------
__global__ __launch_bounds__(256)
void spmm_csr_h_kernel(const int* __restrict__ ptr, const int2* __restrict__ iv,
                       const uint4* __restrict__ xh,
                       float4* __restrict__ out_f, uint4* __restrict__ out_h,
                       const float4* __restrict__ sum_base,
                       float4* __restrict__ sum_out, int n_rows)
{
    int row = blockIdx.x * 16 + (threadIdx.x >> 4);
    if (row >= n_rows) return;
    const int lane = threadIdx.x & 15;   // owns 8 halfs (one uint4)

    int e   = __ldg(ptr + row);
    int end = __ldg(ptr + row + 1);

    float4 a0 = make_float4(0.f, 0.f, 0.f, 0.f);
    float4 a1 = make_float4(0.f, 0.f, 0.f, 0.f);

    for (; e + 4 <= end; e += 4) {
        int2 p0 = __ldg(iv + e);
        int2 p1 = __ldg(iv + e + 1);
        int2 p2 = __ldg(iv + e + 2);
        int2 p3 = __ldg(iv + e + 3);
        uint4 r0 = __ldg(xh + (size_t)p0.x * 16 + lane);
        uint4 r1 = __ldg(xh + (size_t)p1.x * 16 + lane);
        uint4 r2 = __ldg(xh + (size_t)p2.x * 16 + lane);
        uint4 r3 = __ldg(xh + (size_t)p3.x * 16 + lane);
        float v0 = __int_as_float(p0.y), v1 = __int_as_float(p1.y);
        float v2 = __int_as_float(p2.y), v3 = __int_as_float(p3.y);
        float4 u;
        u = unpack_h4(r0.x, r0.y);
        a0.x += v0 * u.x; a0.y += v0 * u.y; a0.z += v0 * u.z; a0.w += v0 * u.w;
        u = unpack_h4(r0.z, r0.w);
        a1.x += v0 * u.x; a1.y += v0 * u.y; a1.z += v0 * u.z; a1.w += v0 * u.w;
        u = unpack_h4(r1.x, r1.y);
        a0.x += v1 * u.x; a0.y += v1 * u.y; a0.z += v1 * u.z; a0.w += v1 * u.w;
        u = unpack_h4(r1.z, r1.w);
        a1.x += v1 * u.x; a1.y += v1 * u.y; a1.z += v1 * u.z; a1.w += v1 * u.w;
        u = unpack_h4(r2.x, r2.y);
        a0.x += v2 * u.x; a0.y += v2 * u.y; a0.z += v2 * u.z; a0.w += v2 * u.w;
        u = unpack_h4(r2.z, r2.w);
        a1.x += v2 * u.x; a1.y += v2 * u.y; a1.z += v2 * u.z; a1.w += v2 * u.w;
        u = unpack_h4(r3.x, r3.y);
        a0.x += v3 * u.x; a0.y += v3 * u.y; a0.z += v3 * u.z; a0.w += v3 * u.w;
        u = unpack_h4(r3.z, r3.w);
        a1.x += v3 * u.x; a1.y += v3 * u.y; a1.z += v3 * u.z; a1.w += v3 * u.w;
    }
    for (; e < end; ++e) {
        int2 p = __ldg(iv + e);
        float v = __int_as_float(p.y);
        uint4 r = __ldg(xh + (size_t)p.x * 16 + lane);
        float4 u;
        u = unpack_h4(r.x, r.y);
        a0.x += v * u.x; a0.y += v * u.y; a0.z += v * u.z; a0.w += v * u.w;
        u = unpack_h4(r.z, r.w);
        a1.x += v * u.x; a1.y += v * u.y; a1.z += v * u.z; a1.w += v * u.w;
    }

    size_t o = (size_t)row * 16 + lane;      // uint4-granular index (8 halfs)
    if (out_h) {
        uint2 h0 = pack_h4(a0);
        uint2 h1 = pack_h4(a1);
        out_h[o] = make_uint4(h0.x, h0.y, h1.x, h1.y);
    }
    float4 t0 = make_float4(a0.x * H_UNSCALE, a0.y * H_UNSCALE,
                            a0.z * H_UNSCALE, a0.w * H_UNSCALE);
    float4 t1 = make_float4(a1.x * H_UNSCALE, a1.y * H_UNSCALE,
                            a1.z * H_UNSCALE, a1.w * H_UNSCALE);
    if (out_f) {
        out_f[2 * o]     = t0;
        out_f[2 * o + 1] = t1;
    }
    if (sum_out) {
        float4 b0 = __ldg(sum_base + 2 * o);
        float4 b1 = __ldg(sum_base + 2 * o + 1);
        b0.x += t0.x; b0.y += t0.y; b0.z += t0.z; b0.w += t0.w;
        b1.x += t1.x; b1.y += t1.y; b1.z += t1.z; b1.w += t1.w;
        sum_out[2 * o]     = b0;
        sum_out[2 * o + 1] = b1;
    }
}

// ---------------------------------------------------------------------------
// Fused gated dense layer with packed FFMA2:
//   msg = concat(a, a*g) @ W + b ;  msg_h = msg * 2^-10 (fp16);  edge_sum = ebase + msg
// Persistent 148 blocks; W (128KB) + X tile (64 rows, 64KB) in dynamic smem.
// 256 threads = 8 warps x 8 rows; lane owns 4 output columns as 2x f32x2.
// ---------------------------------------------------------------------------
__global__ void gemm_gate_kernel(const float* __restrict__ node_msg,
                                 const uint2* __restrict__ group_h,  // scaled fp16
                                 const float* __restrict__ W,        // [2*DIM][DIM]
                                 const float* __restrict__ bias,     // [DIM]
                                 uint2* __restrict__ msg_h,          // scaled fp16 out
                                 const float* __restrict__ ebase,
                                 float* __restrict__ edge_sum,
                                 int n_groups)
{
    extern __shared__ float sm[];
    float4* Wsv = (float4*)sm;                     // 2*DIM*DIM floats (128 KB)
    float4* Xsv = (float4*)(sm + 2 * DIM * DIM);   // 64 rows * 2*DIM floats (64 KB)

    {
        const float4* Wv = (const float4*)W;
        for (int i = threadIdx.x; i < 2 * DIM * DIM / 4; i += blockDim.x)
            Wsv[i] = Wv[i];
    }

    const int warp = threadIdx.x >> 5;
    const int lane = threadIdx.x & 31;
    const float4 bv = ((const float4*)bias)[lane];
    const unsigned long long b_lo = pack2(bv.x, bv.y);
    const unsigned long long b_hi = pack2(bv.z, bv.w);

    const float4* nm4 = (const float4*)node_msg;
    __syncthreads();

    for (int tile = blockIdx.x * 64; tile < n_groups; tile += gridDim.x * 64) {
        // Stage X = [a ; a*g_true] for 64 rows (g_true = g_scaled * 1024, exact)
        for (int i = threadIdx.x; i < 64 * 32; i += 256) {
            int rr = i >> 5;        // row in tile
            int kq = i & 31;        // float4 idx within DIM
            int row = tile + rr;
            float4 a = make_float4(0.f, 0.f, 0.f, 0.f);
            float4 g = make_float4(0.f, 0.f, 0.f, 0.f);
            if (row < n_groups) {
                a = nm4[(size_t)row * 32 + kq];
                uint2 gr = __ldg(group_h + (size_t)row * 32 + kq);
                g = unpack_h4(gr.x, gr.y);
            }
            Xsv[rr * 64 + kq] = a;
            Xsv[rr * 64 + 32 + kq] =
                make_float4(a.x * g.x * H_UNSCALE, a.y * g.y * H_UNSCALE,
                            a.z * g.z * H_UNSCALE, a.w * g.w * H_UNSCALE);
        }
        __syncthreads();

        unsigned long long acc_lo[8], acc_hi[8];
        #pragma unroll
        for (int r = 0; r < 8; r++) { acc_lo[r] = b_lo; acc_hi[r] = b_hi; }

        const float4* Xr = Xsv + warp * 8 * 64;   // this warp's 8 rows

        #pragma unroll 1
        for (int kq = 0; kq < 64; kq++) {         // each kq covers 4 k values
            float4 xr[8];
            #pragma unroll
            for (int r = 0; r < 8; r++) xr[r] = Xr[r * 64 + kq];

            #pragma unroll
            for (int j = 0; j < 4; j++) {
                float4 w = Wsv[(kq * 4 + j) * 32 + lane];
                unsigned long long w_lo = pack2(w.x, w.y);
                unsigned long long w_hi = pack2(w.z, w.w);
                #pragma unroll
                for (int r = 0; r < 8; r++) {
                    float xs = (j == 0) ? xr[r].x : (j == 1) ? xr[r].y
                             : (j == 2) ? xr[r].z : xr[r].w;
                    unsigned long long x2 = pack2(xs, xs);
                    ffma2(acc_lo[r], x2, w_lo);
                    ffma2(acc_hi[r], x2, w_hi);
                }
            }
        }

        const float4* eb = (const float4*)ebase;
        float4* es = (float4*)edge_sum;
        int r0 = tile + warp * 8;
        #pragma unroll
        for (int r = 0; r < 8; r++) {
            int row = r0 + r;
            if (row < n_groups) {
                float2 lo = unpack2(acc_lo[r]);
                float2 hi = unpack2(acc_hi[r]);
                float4 v = make_float4(lo.x, lo.y, hi.x, hi.y);
                size_t oi = (size_t)row * 32 + lane;
                msg_h[oi] = pack_h4(make_float4(v.x * H_SCALE, v.y * H_SCALE,
                                                v.z * H_SCALE, v.w * H_SCALE));
                float4 e = __ldg(eb + oi);
                e.x += v.x; e.y += v.y; e.z += v.z; e.w += v.w;
                es[oi] = e;
            }
        }
        __syncthreads();
    }
}

// ---------------------------------------------------------------------------
extern "C" void kernel_launch(void* const* d_in, const int* in_sizes, int n_in,
                              void* d_out, int out_size)
{
    const float* group_emb = (const float*)d_in[0];
    const float* user_emb  = (const float*)d_in[1];
    const int*   rows      = (const int*)d_in[2];
    const int*   cols      = (const int*)d_in[3];
    const float* vals      = (const float*)d_in[4];
    const float* Ws        = (const float*)d_in[5];
    const float* bs        = (const float*)d_in[6];

    const int n_groups = in_sizes[0] / DIM;
    const int n_users  = in_sizes[1] / DIM;
    const int nnz      = in_sizes[2];
    const int layers   = in_sizes[6] / DIM;

    float* node_sum = (float*)d_out;                          // [n_users, DIM]
    float* edge_sum = (float*)d_out + (size_t)n_users * DIM;  // [n_groups, DIM]

    float* node_msg;
    __half *userh, *msgh_base;
    int *cnt, *ptrA, *workA, *ptrB, *workB;
    int2 *ivA, *ivB;
    cudaGetSymbolAddress((void**)&node_msg, g_node_msg);
    cudaGetSymbolAddress((void**)&userh, g_userh);
    cudaGetSymbolAddress((void**)&msgh_base, g_msgh);
    cudaGetSymbolAddress((void**)&cnt,   g_cnt);
    cudaGetSymbolAddress((void**)&ptrA,  g_ptrA);
    cudaGetSymbolAddress((void**)&workA, g_workA);
    cudaGetSymbolAddress((void**)&ivA,   g_ivA);
    cudaGetSymbolAddress((void**)&ptrB,  g_ptrB);
    cudaGetSymbolAddress((void**)&workB, g_workB);
    cudaGetSymbolAddress((void**)&ivB,   g_ivB);

    int* cntA = cnt;
    int* cntB = cnt + MAX_GROUPS;

    __half* msgh[3] = { msgh_base,
                        msgh_base + (size_t)MAX_GROUPS * DIM,
                        msgh_base + 2 * (size_t)MAX_GROUPS * DIM };

    // ---- conv(both embeddings) + zero(counters, scan flags), one launch ----
    {
        int n4u = n_users * DIM / 4;
        int n4g = n_groups * DIM / 4;
        int n4 = n4u + n4g;
        f32_to_f16_dual_kernel<<<(n4 + 255) / 256, 256>>>(
            (const float4*)user_emb, (uint2*)userh, n4u,
            (const float4*)group_emb, (uint2*)msgh[2], n4g,
            MAX_GROUPS + n_users);
    }

    // ---- Build CSR (by group row) and CSC (by user col), in-graph ----
    hist_kernel<<<(nnz + 255) / 256, 256>>>(rows, cols, cntA, cntB, nnz);

    const int nbA = (n_groups + 1023) / 1024;
    const int nbB = (n_users + 1023) / 1024;
    scan_lookback_kernel<<<nbA + nbB, 1024>>>(cntA, ptrA + 1, workA, ptrA, n_groups, nbA,
                                              cntB, ptrB + 1, workB, ptrB, n_users);

    scatter_kernel<<<(nnz + 255) / 256, 256>>>(rows, cols, vals, workA, ivA, workB, ivB, nnz);

    // ---- Layers ----
    const int smem_bytes = (2 * DIM * DIM + 64 * 2 * DIM) * sizeof(float);
    cudaFuncSetAttribute(gemm_gate_kernel,
                         cudaFuncAttributeMaxDynamicSharedMemorySize, smem_bytes);

    const int spmmA_blocks = (n_groups + 15) / 16;   // 16 rows per 256-thread block
    const int spmmB_blocks = (n_users + 15) / 16;

    int cur = 2;   // group_cur slot (starts at converted group_emb)
    int nxt = 0;

    for (int i = 0; i < layers; i++) {
        // node_msg = H @ user_h   (scaled fp16 gather, fp32 out)
        spmm_csr_h_kernel<<<spmmA_blocks, 256>>>(ptrA, ivA, (const uint4*)userh,
                                                 (float4*)node_msg, nullptr,
                                                 nullptr, nullptr, n_groups);

        // msg_h = fp16(msg * 2^-10); edge_sum = (i==0 ? group_emb : edge_sum) + msg
        const float* ebase = (i == 0) ? group_emb : edge_sum;
        gemm_gate_kernel<<<148, 256, smem_bytes>>>(
            node_msg, (const uint2*)msgh[cur],
            Ws + (size_t)i * 2 * DIM * DIM, bs + (size_t)i * DIM,
            (uint2*)msgh[nxt], ebase, edge_sum, n_groups);

        // user_h = scaled fp16(H^T @ msg) ; node_sum = (i==0 ? user_emb : node_sum) + true
        // Last layer: user_h dead — skip fp16 store.
        const float* nbase = (i == 0) ? user_emb : node_sum;
        uint4* uh_out = (i == layers - 1) ? nullptr : (uint4*)userh;
        spmm_csr_h_kernel<<<spmmB_blocks, 256>>>(ptrB, ivB, (const uint4*)msgh[nxt],
                                                 nullptr, uh_out,
                                                 (const float4*)nbase, (float4*)node_sum,
                                                 n_users);

        cur = nxt;
        nxt = (nxt == 0) ? 1 : 0;
    }
}

// round 14
// speedup vs baseline: 1.0112x; 1.0112x over previous
#include <cuda_runtime.h>
#include <cuda_fp16.h>
#include <cstddef>

#define DIM 128
#define MAX_GROUPS 50000
#define MAX_USERS  200000
#define MAX_NNZ    2000000

#define H_SCALE   0.0009765625f   // 2^-10 (exact)
#define H_UNSCALE 1024.0f         // 2^10  (exact)

// ---------------------------------------------------------------------------
// Scratch (device globals; no allocation allowed)
// ---------------------------------------------------------------------------
__device__ float g_node_msg[(size_t)MAX_GROUPS * DIM];
__device__ __half g_userh[(size_t)MAX_USERS * DIM];          // fp16 user operand (scaled 2^-10)
__device__ __half g_msgh[3][(size_t)MAX_GROUPS * DIM];       // fp16 msg slots (scaled 2^-10)

// cntA | cntB | scan flags (1024 ints = 512 ull) — one memset zeroes all
__device__ int  g_build[MAX_GROUPS + MAX_USERS + 1024];
__device__ int  g_ptrA[MAX_GROUPS + 1];
__device__ int  g_workA[MAX_GROUPS];
__device__ int2 g_ivA[MAX_NNZ];          // CSR by group row: (user_col, val)

__device__ int  g_ptrB[MAX_USERS + 1];
__device__ int  g_workB[MAX_USERS];
__device__ int2 g_ivB[MAX_NNZ];          // CSC by user col: (group_row, val)

// ---------------------------------------------------------------------------
// f32x2 packed-math helpers (Blackwell FFMA2 via PTX)
// ---------------------------------------------------------------------------
__device__ __forceinline__ unsigned long long pack2(float lo, float hi)
{
    unsigned long long r;
    asm("mov.b64 %0, {%1, %2};" : "=l"(r) : "f"(lo), "f"(hi));
    return r;
}
__device__ __forceinline__ void ffma2(unsigned long long& d,
                                      unsigned long long a, unsigned long long b)
{
    asm("fma.rn.f32x2 %0, %1, %2, %0;" : "+l"(d) : "l"(a), "l"(b));
}
__device__ __forceinline__ float2 unpack2(unsigned long long v)
{
    float2 r;
    asm("mov.b64 {%0, %1}, %2;" : "=f"(r.x), "=f"(r.y) : "l"(v));
    return r;
}

// unpack 4 halfs -> float4
__device__ __forceinline__ float4 unpack_h4(unsigned lo, unsigned hi)
{
    __half2 h0 = *reinterpret_cast<__half2*>(&lo);
    __half2 h1 = *reinterpret_cast<__half2*>(&hi);
    float2 a = __half22float2(h0);
    float2 b = __half22float2(h1);
    return make_float4(a.x, a.y, b.x, b.y);
}
// pack float4 -> 4 halfs (uint2)
__device__ __forceinline__ uint2 pack_h4(float4 v)
{
    __half2 h0 = __floats2half2_rn(v.x, v.y);
    __half2 h1 = __floats2half2_rn(v.z, v.w);
    uint2 r;
    r.x = *reinterpret_cast<unsigned*>(&h0);
    r.y = *reinterpret_cast<unsigned*>(&h1);
    return r;
}

// ---------------------------------------------------------------------------
// Merged: fp32 -> scaled fp16 conversion of BOTH embeddings  +  batched
// histogram (4 edges/thread, int4 loads). Counters pre-zeroed by memset.
// Conversion and histogram are independent -> they overlap in one launch.
__global__ void conv_hist_kernel(const float4* __restrict__ a, uint2* __restrict__ oa, int n4a,
                                 const float4* __restrict__ b, uint2* __restrict__ ob, int n4b,
                                 const int* __restrict__ rows, const int* __restrict__ cols,
                                 int* __restrict__ cntA, int* __restrict__ cntB, int nnz)
{
    int i = blockIdx.x * blockDim.x + threadIdx.x;

    // conversion part
    if (i < n4a) {
        float4 v = a[i];
        v.x *= H_SCALE; v.y *= H_SCALE; v.z *= H_SCALE; v.w *= H_SCALE;
        oa[i] = pack_h4(v);
    } else if (i < n4a + n4b) {
        int j = i - n4a;
        float4 v = b[j];
        v.x *= H_SCALE; v.y *= H_SCALE; v.z *= H_SCALE; v.w *= H_SCALE;
        ob[j] = pack_h4(v);
    }

    // histogram part: 4 edges per thread
    int j = i * 4;
    if (j + 3 < nnz) {
        int4 r4 = *(const int4*)(rows + j);
        int4 c4 = *(const int4*)(cols + j);
        atomicAdd(cntA + r4.x, 1); atomicAdd(cntB + c4.x, 1);
        atomicAdd(cntA + r4.y, 1); atomicAdd(cntB + c4.y, 1);
        atomicAdd(cntA + r4.z, 1); atomicAdd(cntB + c4.z, 1);
        atomicAdd(cntA + r4.w, 1); atomicAdd(cntB + c4.w, 1);
    } else if (j < nnz) {
        for (int k = j; k < nnz; k++) {
            atomicAdd(cntA + rows[k], 1);
            atomicAdd(cntB + cols[k], 1);
        }
    }
}

// ---------------------------------------------------------------------------
// Single-pass decoupled-lookback scan over both segments (A then B).
// out (= ptr+1) gets the inclusive scan; work gets the exclusive start.
__global__ __launch_bounds__(1024)
void scan_lookback_kernel(const int* __restrict__ cntA, int* __restrict__ outA,
                          int* __restrict__ workA, int* __restrict__ ptrA0,
                          int nA, int nbA,
                          const int* __restrict__ cntB, int* __restrict__ outB,
                          int* __restrict__ workB, int* __restrict__ ptrB0,
                          int nB, unsigned long long* __restrict__ flagbase)
{
    __shared__ int sm[1024];
    __shared__ int s_prefix;

    const int* cnt; int* out; int* work; int* p0; int n; int bid;
    unsigned long long* flags;
    if ((int)blockIdx.x < nbA) {
        cnt = cntA; out = outA; work = workA; p0 = ptrA0; n = nA;
        bid = blockIdx.x; flags = flagbase;
    } else {
        cnt = cntB; out = outB; work = workB; p0 = ptrB0; n = nB;
        bid = blockIdx.x - nbA; flags = flagbase + 256;
    }

    int i = bid * 1024 + threadIdx.x;
    int v = (i < n) ? cnt[i] : 0;
    sm[threadIdx.x] = v;
    __syncthreads();
    for (int off = 1; off < 1024; off <<= 1) {
        int t = (threadIdx.x >= off) ? sm[threadIdx.x - off] : 0;
        __syncthreads();
        sm[threadIdx.x] += t;
        __syncthreads();
    }

    if (threadIdx.x == 0) {
        int agg = sm[1023];
        if (bid == 0) {
            atomicExch(&flags[0], (2ull << 32) | (unsigned)agg);
            s_prefix = 0;
        } else {
            atomicExch(&flags[bid], (1ull << 32) | (unsigned)agg);
            int running = 0;
            int j = bid - 1;
            while (j >= 0) {
                unsigned long long f = atomicAdd(&flags[j], 0ull);
                unsigned st = (unsigned)(f >> 32);
                if (st == 0) continue;            // spin: predecessor not ready
                running += (int)(unsigned)f;
                if (st == 2) break;               // hit a full prefix
                j--;
            }
            atomicExch(&flags[bid], (2ull << 32) | (unsigned)(running + agg));
            s_prefix = running;
        }
        if (bid == 0) *p0 = 0;
    }
    __syncthreads();

    if (i < n) {
        int incl = sm[threadIdx.x] + s_prefix;
        out[i] = incl;
        work[i] = incl - v;
    }
}

// ---------------------------------------------------------------------------
// Batched scatter: 4 edges per thread, int4/float4 loads -> 4 independent
// atomic->store chains in flight (attacks the 600-cyc latency binding).
__global__ void scatter_kernel(const int* __restrict__ rows, const int* __restrict__ cols,
                               const float* __restrict__ vals,
                               int* __restrict__ workA, int2* __restrict__ ivA,
                               int* __restrict__ workB, int2* __restrict__ ivB, int nnz)
{
    int j = (blockIdx.x * blockDim.x + threadIdx.x) * 4;
    if (j + 3 < nnz) {
        int4   r4 = *(const int4*)(rows + j);
        int4   c4 = *(const int4*)(cols + j);
        float4 v4 = *(const float4*)(vals + j);
        int pa0 = atomicAdd(workA + r4.x, 1);
        int pa1 = atomicAdd(workA + r4.y, 1);
        int pa2 = atomicAdd(workA + r4.z, 1);
        int pa3 = atomicAdd(workA + r4.w, 1);
        int pb0 = atomicAdd(workB + c4.x, 1);
        int pb1 = atomicAdd(workB + c4.y, 1);
        int pb2 = atomicAdd(workB + c4.z, 1);
        int pb3 = atomicAdd(workB + c4.w, 1);
        ivA[pa0] = make_int2(c4.x, __float_as_int(v4.x));
        ivA[pa1] = make_int2(c4.y, __float_as_int(v4.y));
        ivA[pa2] = make_int2(c4.z, __float_as_int(v4.z));
        ivA[pa3] = make_int2(c4.w, __float_as_int(v4.w));
        ivB[pb0] = make_int2(r4.x, __float_as_int(v4.x));
        ivB[pb1] = make_int2(r4.y, __float_as_int(v4.y));
        ivB[pb2] = make_int2(r4.z, __float_as_int(v4.z));
        ivB[pb3] = make_int2(r4.w, __float_as_int(v4.w));
    } else if (j < nnz) {
        for (int k = j; k < nnz; k++) {
            int r = rows[k], c = cols[k];
            int v = __float_as_int(vals[k]);
            int pa = atomicAdd(workA + r, 1);
            ivA[pa] = make_int2(c, v);
            int pb = atomicAdd(workB + c, 1);
            ivB[pb] = make_int2(r, v);
        }
    }
}

// ---------------------------------------------------------------------------
// CSR SpMM, HALF-WARP per row (16 lanes x LDG.128 = 256B fp16 row):
// unroll-4 main loop + serial tail (known-good R9/R11 form).
//   if (out_h)   out_h[row]   = acc_raw    (fp16, scaled domain)
//   if (out_f)   out_f[row]   = acc_raw * 1024
//   if (sum_out) sum_out[row] = sum_base[row] + acc_raw * 1024
// ---------------------------------------------------------------------------
__global__ __launch_bounds__(256)
void spmm_csr_h_kernel(const int* __restrict__ ptr, const int2* __restrict__ iv,
                       const uint4* __restrict__ xh,
                       float4* __restrict__ out_f, uint4* __restrict__ out_h,
                       const float4* __restrict__ sum_base,
                       float4* __restrict__ sum_out, int n_rows)
{
    int row = blockIdx.x * 16 + (threadIdx.x >> 4);
    if (row >= n_rows) return;
    const int lane = threadIdx.x & 15;   // owns 8 halfs (one uint4)

    int e   = __ldg(ptr + row);
    int end = __ldg(ptr + row + 1);

    float4 a0 = make_float4(0.f, 0.f, 0.f, 0.f);
    float4 a1 = make_float4(0.f, 0.f, 0.f, 0.f);

    for (; e + 4 <= end; e += 4) {
        int2 p0 = __ldg(iv + e);
        int2 p1 = __ldg(iv + e + 1);
        int2 p2 = __ldg(iv + e + 2);
        int2 p3 = __ldg(iv + e + 3);
        uint4 r0 = __ldg(xh + (size_t)p0.x * 16 + lane);
        uint4 r1 = __ldg(xh + (size_t)p1.x * 16 + lane);
        uint4 r2 = __ldg(xh + (size_t)p2.x * 16 + lane);
        uint4 r3 = __ldg(xh + (size_t)p3.x * 16 + lane);
        float v0 = __int_as_float(p0.y), v1 = __int_as_float(p1.y);
        float v2 = __int_as_float(p2.y), v3 = __int_as_float(p3.y);
        float4 u;
        u = unpack_h4(r0.x, r0.y);
        a0.x += v0 * u.x; a0.y += v0 * u.y; a0.z += v0 * u.z; a0.w += v0 * u.w;
        u = unpack_h4(r0.z, r0.w);
        a1.x += v0 * u.x; a1.y += v0 * u.y; a1.z += v0 * u.z; a1.w += v0 * u.w;
        u = unpack_h4(r1.x, r1.y);
        a0.x += v1 * u.x; a0.y += v1 * u.y; a0.z += v1 * u.z; a0.w += v1 * u.w;
        u = unpack_h4(r1.z, r1.w);
        a1.x += v1 * u.x; a1.y += v1 * u.y; a1.z += v1 * u.z; a1.w += v1 * u.w;
        u = unpack_h4(r2.x, r2.y);
        a0.x += v2 * u.x; a0.y += v2 * u.y; a0.z += v2 * u.z; a0.w += v2 * u.w;
        u = unpack_h4(r2.z, r2.w);
        a1.x += v2 * u.x; a1.y += v2 * u.y; a1.z += v2 * u.z; a1.w += v2 * u.w;
        u = unpack_h4(r3.x, r3.y);
        a0.x += v3 * u.x; a0.y += v3 * u.y; a0.z += v3 * u.z; a0.w += v3 * u.w;
        u = unpack_h4(r3.z, r3.w);
        a1.x += v3 * u.x; a1.y += v3 * u.y; a1.z += v3 * u.z; a1.w += v3 * u.w;
    }
    for (; e < end; ++e) {
        int2 p = __ldg(iv + e);
        float v = __int_as_float(p.y);
        uint4 r = __ldg(xh + (size_t)p.x * 16 + lane);
        float4 u;
        u = unpack_h4(r.x, r.y);
        a0.x += v * u.x; a0.y += v * u.y; a0.z += v * u.z; a0.w += v * u.w;
        u = unpack_h4(r.z, r.w);
        a1.x += v * u.x; a1.y += v * u.y; a1.z += v * u.z; a1.w += v * u.w;
    }

    size_t o = (size_t)row * 16 + lane;      // uint4-granular index (8 halfs)
    if (out_h) {
        uint2 h0 = pack_h4(a0);
        uint2 h1 = pack_h4(a1);
        out_h[o] = make_uint4(h0.x, h0.y, h1.x, h1.y);
    }
    float4 t0 = make_float4(a0.x * H_UNSCALE, a0.y * H_UNSCALE,
                            a0.z * H_UNSCALE, a0.w * H_UNSCALE);
    float4 t1 = make_float4(a1.x * H_UNSCALE, a1.y * H_UNSCALE,
                            a1.z * H_UNSCALE, a1.w * H_UNSCALE);
    if (out_f) {
        out_f[2 * o]     = t0;
        out_f[2 * o + 1] = t1;
    }
    if (sum_out) {
        float4 b0 = __ldg(sum_base + 2 * o);
        float4 b1 = __ldg(sum_base + 2 * o + 1);
        b0.x += t0.x; b0.y += t0.y; b0.z += t0.z; b0.w += t0.w;
        b1.x += t1.x; b1.y += t1.y; b1.z += t1.z; b1.w += t1.w;
        sum_out[2 * o]     = b0;
        sum_out[2 * o + 1] = b1;
    }
}

// ---------------------------------------------------------------------------
// Fused gated dense layer with packed FFMA2:
//   msg = concat(a, a*g) @ W + b ;  msg_h = msg * 2^-10 (fp16);  edge_sum = ebase + msg
// Persistent 148 blocks; W (128KB) + X tile (64 rows, 64KB) in dynamic smem.
// 256 threads = 8 warps x 8 rows; lane owns 4 output columns as 2x f32x2.
// ---------------------------------------------------------------------------
__global__ void gemm_gate_kernel(const float* __restrict__ node_msg,
                                 const uint2* __restrict__ group_h,  // scaled fp16
                                 const float* __restrict__ W,        // [2*DIM][DIM]
                                 const float* __restrict__ bias,     // [DIM]
                                 uint2* __restrict__ msg_h,          // scaled fp16 out
                                 const float* __restrict__ ebase,
                                 float* __restrict__ edge_sum,
                                 int n_groups)
{
    extern __shared__ float sm[];
    float4* Wsv = (float4*)sm;                     // 2*DIM*DIM floats (128 KB)
    float4* Xsv = (float4*)(sm + 2 * DIM * DIM);   // 64 rows * 2*DIM floats (64 KB)

    {
        const float4* Wv = (const float4*)W;
        for (int i = threadIdx.x; i < 2 * DIM * DIM / 4; i += blockDim.x)
            Wsv[i] = Wv[i];
    }

    const int warp = threadIdx.x >> 5;
    const int lane = threadIdx.x & 31;
    const float4 bv = ((const float4*)bias)[lane];
    const unsigned long long b_lo = pack2(bv.x, bv.y);
    const unsigned long long b_hi = pack2(bv.z, bv.w);

    const float4* nm4 = (const float4*)node_msg;
    __syncthreads();

    for (int tile = blockIdx.x * 64; tile < n_groups; tile += gridDim.x * 64) {
        // Stage X = [a ; a*g_true] for 64 rows (g_true = g_scaled * 1024, exact)
        for (int i = threadIdx.x; i < 64 * 32; i += 256) {
            int rr = i >> 5;        // row in tile
            int kq = i & 31;        // float4 idx within DIM
            int row = tile + rr;
            float4 a = make_float4(0.f, 0.f, 0.f, 0.f);
            float4 g = make_float4(0.f, 0.f, 0.f, 0.f);
            if (row < n_groups) {
                a = nm4[(size_t)row * 32 + kq];
                uint2 gr = __ldg(group_h + (size_t)row * 32 + kq);
                g = unpack_h4(gr.x, gr.y);
            }
            Xsv[rr * 64 + kq] = a;
            Xsv[rr * 64 + 32 + kq] =
                make_float4(a.x * g.x * H_UNSCALE, a.y * g.y * H_UNSCALE,
                            a.z * g.z * H_UNSCALE, a.w * g.w * H_UNSCALE);
        }
        __syncthreads();

        unsigned long long acc_lo[8], acc_hi[8];
        #pragma unroll
        for (int r = 0; r < 8; r++) { acc_lo[r] = b_lo; acc_hi[r] = b_hi; }

        const float4* Xr = Xsv + warp * 8 * 64;   // this warp's 8 rows

        #pragma unroll 1
        for (int kq = 0; kq < 64; kq++) {         // each kq covers 4 k values
            float4 xr[8];
            #pragma unroll
            for (int r = 0; r < 8; r++) xr[r] = Xr[r * 64 + kq];

            #pragma unroll
            for (int j = 0; j < 4; j++) {
                float4 w = Wsv[(kq * 4 + j) * 32 + lane];
                unsigned long long w_lo = pack2(w.x, w.y);
                unsigned long long w_hi = pack2(w.z, w.w);
                #pragma unroll
                for (int r = 0; r < 8; r++) {
                    float xs = (j == 0) ? xr[r].x : (j == 1) ? xr[r].y
                             : (j == 2) ? xr[r].z : xr[r].w;
                    unsigned long long x2 = pack2(xs, xs);
                    ffma2(acc_lo[r], x2, w_lo);
                    ffma2(acc_hi[r], x2, w_hi);
                }
            }
        }

        const float4* eb = (const float4*)ebase;
        float4* es = (float4*)edge_sum;
        int r0 = tile + warp * 8;
        #pragma unroll
        for (int r = 0; r < 8; r++) {
            int row = r0 + r;
            if (row < n_groups) {
                float2 lo = unpack2(acc_lo[r]);
                float2 hi = unpack2(acc_hi[r]);
                float4 v = make_float4(lo.x, lo.y, hi.x, hi.y);
                size_t oi = (size_t)row * 32 + lane;
                msg_h[oi] = pack_h4(make_float4(v.x * H_SCALE, v.y * H_SCALE,
                                                v.z * H_SCALE, v.w * H_SCALE));
                float4 e = __ldg(eb + oi);
                e.x += v.x; e.y += v.y; e.z += v.z; e.w += v.w;
                es[oi] = e;
            }
        }
        __syncthreads();
    }
}

// ---------------------------------------------------------------------------
extern "C" void kernel_launch(void* const* d_in, const int* in_sizes, int n_in,
                              void* d_out, int out_size)
{
    const float* group_emb = (const float*)d_in[0];
    const float* user_emb  = (const float*)d_in[1];
    const int*   rows      = (const int*)d_in[2];
    const int*   cols      = (const int*)d_in[3];
    const float* vals      = (const float*)d_in[4];
    const float* Ws        = (const float*)d_in[5];
    const float* bs        = (const float*)d_in[6];

    const int n_groups = in_sizes[0] / DIM;
    const int n_users  = in_sizes[1] / DIM;
    const int nnz      = in_sizes[2];
    const int layers   = in_sizes[6] / DIM;

    float* node_sum = (float*)d_out;                          // [n_users, DIM]
    float* edge_sum = (float*)d_out + (size_t)n_users * DIM;  // [n_groups, DIM]

    float* node_msg;
    __half *userh, *msgh_base;
    int *build, *ptrA, *workA, *ptrB, *workB;
    int2 *ivA, *ivB;
    cudaGetSymbolAddress((void**)&node_msg, g_node_msg);
    cudaGetSymbolAddress((void**)&userh, g_userh);
    cudaGetSymbolAddress((void**)&msgh_base, g_msgh);
    cudaGetSymbolAddress((void**)&build, g_build);
    cudaGetSymbolAddress((void**)&ptrA,  g_ptrA);
    cudaGetSymbolAddress((void**)&workA, g_workA);
    cudaGetSymbolAddress((void**)&ivA,   g_ivA);
    cudaGetSymbolAddress((void**)&ptrB,  g_ptrB);
    cudaGetSymbolAddress((void**)&workB, g_workB);
    cudaGetSymbolAddress((void**)&ivB,   g_ivB);

    int* cntA = build;
    int* cntB = build + MAX_GROUPS;
    unsigned long long* flags = (unsigned long long*)(build + MAX_GROUPS + MAX_USERS);

    __half* msgh[3] = { msgh_base,
                        msgh_base + (size_t)MAX_GROUPS * DIM,
                        msgh_base + 2 * (size_t)MAX_GROUPS * DIM };

    // ---- zero counters + scan flags (one memset) ----
    cudaMemsetAsync(build, 0, ((size_t)MAX_GROUPS + n_users + 1024) * sizeof(int), 0);

    // ---- conversion + histogram merged (independent work, one launch) ----
    {
        int n4u = n_users * DIM / 4;
        int n4g = n_groups * DIM / 4;
        int nconv = n4u + n4g;
        int nhist = (nnz + 3) / 4;
        int nthreads = (nconv > nhist) ? nconv : nhist;
        conv_hist_kernel<<<(nthreads + 255) / 256, 256>>>(
            (const float4*)user_emb, (uint2*)userh, n4u,
            (const float4*)group_emb, (uint2*)msgh[2], n4g,
            rows, cols, cntA, cntB, nnz);
    }

    // ---- scan + scatter ----
    const int nbA = (n_groups + 1023) / 1024;
    const int nbB = (n_users + 1023) / 1024;
    scan_lookback_kernel<<<nbA + nbB, 1024>>>(cntA, ptrA + 1, workA, ptrA, n_groups, nbA,
                                              cntB, ptrB + 1, workB, ptrB, n_users, flags);

    {
        int nsc = (nnz + 3) / 4;
        scatter_kernel<<<(nsc + 255) / 256, 256>>>(rows, cols, vals,
                                                   workA, ivA, workB, ivB, nnz);
    }

    // ---- Layers ----
    const int smem_bytes = (2 * DIM * DIM + 64 * 2 * DIM) * sizeof(float);
    cudaFuncSetAttribute(gemm_gate_kernel,
                         cudaFuncAttributeMaxDynamicSharedMemorySize, smem_bytes);

    const int spmmA_blocks = (n_groups + 15) / 16;   // 16 rows per 256-thread block
    const int spmmB_blocks = (n_users + 15) / 16;

    int cur = 2;   // group_cur slot (starts at converted group_emb)
    int nxt = 0;

    for (int i = 0; i < layers; i++) {
        // node_msg = H @ user_h   (scaled fp16 gather, fp32 out)
        spmm_csr_h_kernel<<<spmmA_blocks, 256>>>(ptrA, ivA, (const uint4*)userh,
                                                 (float4*)node_msg, nullptr,
                                                 nullptr, nullptr, n_groups);

        // msg_h = fp16(msg * 2^-10); edge_sum = (i==0 ? group_emb : edge_sum) + msg
        const float* ebase = (i == 0) ? group_emb : edge_sum;
        gemm_gate_kernel<<<148, 256, smem_bytes>>>(
            node_msg, (const uint2*)msgh[cur],
            Ws + (size_t)i * 2 * DIM * DIM, bs + (size_t)i * DIM,
            (uint2*)msgh[nxt], ebase, edge_sum, n_groups);

        // user_h = scaled fp16(H^T @ msg) ; node_sum = (i==0 ? user_emb : node_sum) + true
        // Last layer: user_h dead — skip fp16 store.
        const float* nbase = (i == 0) ? user_emb : node_sum;
        uint4* uh_out = (i == layers - 1) ? nullptr : (uint4*)userh;
        spmm_csr_h_kernel<<<spmmB_blocks, 256>>>(ptrB, ivB, (const uint4*)msgh[nxt],
                                                 nullptr, uh_out,
                                                 (const float4*)nbase, (float4*)node_sum,
                                                 n_users);

        cur = nxt;
        nxt = (nxt == 0) ? 1 : 0;
    }
}

// round 17
// speedup vs baseline: 1.1524x; 1.1396x over previous
#include <cuda_runtime.h>
#include <cuda_fp16.h>
#include <cstddef>

#define DIM 128
#define MAX_GROUPS 50000
#define MAX_USERS  200000
#define MAX_NNZ    2000000

#define H_SCALE   0.0009765625f   // 2^-10 (exact)
#define H_UNSCALE 1024.0f         // 2^10  (exact)

// ---------------------------------------------------------------------------
// Scratch (device globals; no allocation allowed)
// ---------------------------------------------------------------------------
__device__ float g_node_msg[(size_t)MAX_GROUPS * DIM];
__device__ __half g_userh[2][(size_t)MAX_USERS * DIM];       // scaled fp16 user slots
__device__ __half g_msgh[3][(size_t)MAX_GROUPS * DIM];       // scaled fp16 msg slots

// cntA | cntB | scan flags (1024 ints = 512 ull) — one memset zeroes all
__device__ int  g_build[MAX_GROUPS + MAX_USERS + 1024];
__device__ int  g_ptrA[MAX_GROUPS + 1];
__device__ int  g_workA[MAX_GROUPS];
__device__ int2 g_ivA[MAX_NNZ];          // CSR by group row: (user_col, val)

__device__ int  g_ptrB[MAX_USERS + 1];
__device__ int  g_workB[MAX_USERS];
__device__ int2 g_ivB[MAX_NNZ];          // CSC by user col: (group_row, val)

// ---------------------------------------------------------------------------
// f32x2 packed-math helpers (Blackwell FFMA2 via PTX)
// ---------------------------------------------------------------------------
__device__ __forceinline__ unsigned long long pack2(float lo, float hi)
{
    unsigned long long r;
    asm("mov.b64 %0, {%1, %2};" : "=l"(r) : "f"(lo), "f"(hi));
    return r;
}
__device__ __forceinline__ void ffma2(unsigned long long& d,
                                      unsigned long long a, unsigned long long b)
{
    asm("fma.rn.f32x2 %0, %1, %2, %0;" : "+l"(d) : "l"(a), "l"(b));
}
__device__ __forceinline__ float2 unpack2(unsigned long long v)
{
    float2 r;
    asm("mov.b64 {%0, %1}, %2;" : "=f"(r.x), "=f"(r.y) : "l"(v));
    return r;
}

// unpack 4 halfs -> float4
__device__ __forceinline__ float4 unpack_h4(unsigned lo, unsigned hi)
{
    __half2 h0 = *reinterpret_cast<__half2*>(&lo);
    __half2 h1 = *reinterpret_cast<__half2*>(&hi);
    float2 a = __half22float2(h0);
    float2 b = __half22float2(h1);
    return make_float4(a.x, a.y, b.x, b.y);
}
// pack float4 -> 4 halfs (uint2)
__device__ __forceinline__ uint2 pack_h4(float4 v)
{
    __half2 h0 = __floats2half2_rn(v.x, v.y);
    __half2 h1 = __floats2half2_rn(v.z, v.w);
    uint2 r;
    r.x = *reinterpret_cast<unsigned*>(&h0);
    r.y = *reinterpret_cast<unsigned*>(&h1);
    return r;
}

// ---------------------------------------------------------------------------
// Merged: fp32 -> scaled fp16 conversion of BOTH embeddings  +  batched
// histogram (4 edges/thread, int4 loads). Counters pre-zeroed by memset.
__global__ void conv_hist_kernel(const float4* __restrict__ a, uint2* __restrict__ oa, int n4a,
                                 const float4* __restrict__ b, uint2* __restrict__ ob, int n4b,
                                 const int* __restrict__ rows, const int* __restrict__ cols,
                                 int* __restrict__ cntA, int* __restrict__ cntB, int nnz)
{
    int i = blockIdx.x * blockDim.x + threadIdx.x;

    if (i < n4a) {
        float4 v = a[i];
        v.x *= H_SCALE; v.y *= H_SCALE; v.z *= H_SCALE; v.w *= H_SCALE;
        oa[i] = pack_h4(v);
    } else if (i < n4a + n4b) {
        int j = i - n4a;
        float4 v = b[j];
        v.x *= H_SCALE; v.y *= H_SCALE; v.z *= H_SCALE; v.w *= H_SCALE;
        ob[j] = pack_h4(v);
    }

    int j = i * 4;
    if (j + 3 < nnz) {
        int4 r4 = *(const int4*)(rows + j);
        int4 c4 = *(const int4*)(cols + j);
        atomicAdd(cntA + r4.x, 1); atomicAdd(cntB + c4.x, 1);
        atomicAdd(cntA + r4.y, 1); atomicAdd(cntB + c4.y, 1);
        atomicAdd(cntA + r4.z, 1); atomicAdd(cntB + c4.z, 1);
        atomicAdd(cntA + r4.w, 1); atomicAdd(cntB + c4.w, 1);
    } else if (j < nnz) {
        for (int k = j; k < nnz; k++) {
            atomicAdd(cntA + rows[k], 1);
            atomicAdd(cntB + cols[k], 1);
        }
    }
}

// ---------------------------------------------------------------------------
// Single-pass decoupled-lookback scan over both segments (A then B).
__global__ __launch_bounds__(1024)
void scan_lookback_kernel(const int* __restrict__ cntA, int* __restrict__ outA,
                          int* __restrict__ workA, int* __restrict__ ptrA0,
                          int nA, int nbA,
                          const int* __restrict__ cntB, int* __restrict__ outB,
                          int* __restrict__ workB, int* __restrict__ ptrB0,
                          int nB, unsigned long long* __restrict__ flagbase)
{
    __shared__ int sm[1024];
    __shared__ int s_prefix;

    const int* cnt; int* out; int* work; int* p0; int n; int bid;
    unsigned long long* flags;
    if ((int)blockIdx.x < nbA) {
        cnt = cntA; out = outA; work = workA; p0 = ptrA0; n = nA;
        bid = blockIdx.x; flags = flagbase;
    } else {
        cnt = cntB; out = outB; work = workB; p0 = ptrB0; n = nB;
        bid = blockIdx.x - nbA; flags = flagbase + 256;
    }

    int i = bid * 1024 + threadIdx.x;
    int v = (i < n) ? cnt[i] : 0;
    sm[threadIdx.x] = v;
    __syncthreads();
    for (int off = 1; off < 1024; off <<= 1) {
        int t = (threadIdx.x >= off) ? sm[threadIdx.x - off] : 0;
        __syncthreads();
        sm[threadIdx.x] += t;
        __syncthreads();
    }

    if (threadIdx.x == 0) {
        int agg = sm[1023];
        if (bid == 0) {
            atomicExch(&flags[0], (2ull << 32) | (unsigned)agg);
            s_prefix = 0;
        } else {
            atomicExch(&flags[bid], (1ull << 32) | (unsigned)agg);
            int running = 0;
            int j = bid - 1;
            while (j >= 0) {
                unsigned long long f = atomicAdd(&flags[j], 0ull);
                unsigned st = (unsigned)(f >> 32);
                if (st == 0) continue;
                running += (int)(unsigned)f;
                if (st == 2) break;
                j--;
            }
            atomicExch(&flags[bid], (2ull << 32) | (unsigned)(running + agg));
            s_prefix = running;
        }
        if (bid == 0) *p0 = 0;
    }
    __syncthreads();

    if (i < n) {
        int incl = sm[threadIdx.x] + s_prefix;
        out[i] = incl;
        work[i] = incl - v;
    }
}

// ---------------------------------------------------------------------------
// Batched scatter: 4 edges per thread (4 independent atomic->store chains).
__global__ void scatter_kernel(const int* __restrict__ rows, const int* __restrict__ cols,
                               const float* __restrict__ vals,
                               int* __restrict__ workA, int2* __restrict__ ivA,
                               int* __restrict__ workB, int2* __restrict__ ivB, int nnz)
{
    int j = (blockIdx.x * blockDim.x + threadIdx.x) * 4;
    if (j + 3 < nnz) {
        int4   r4 = *(const int4*)(rows + j);
        int4   c4 = *(const int4*)(cols + j);
        float4 v4 = *(const float4*)(vals + j);
        int pa0 = atomicAdd(workA + r4.x, 1);
        int pa1 = atomicAdd(workA + r4.y, 1);
        int pa2 = atomicAdd(workA + r4.z, 1);
        int pa3 = atomicAdd(workA + r4.w, 1);
        int pb0 = atomicAdd(workB + c4.x, 1);
        int pb1 = atomicAdd(workB + c4.y, 1);
        int pb2 = atomicAdd(workB + c4.z, 1);
        int pb3 = atomicAdd(workB + c4.w, 1);
        ivA[pa0] = make_int2(c4.x, __float_as_int(v4.x));
        ivA[pa1] = make_int2(c4.y, __float_as_int(v4.y));
        ivA[pa2] = make_int2(c4.z, __float_as_int(v4.z));
        ivA[pa3] = make_int2(c4.w, __float_as_int(v4.w));
        ivB[pb0] = make_int2(r4.x, __float_as_int(v4.x));
        ivB[pb1] = make_int2(r4.y, __float_as_int(v4.y));
        ivB[pb2] = make_int2(r4.z, __float_as_int(v4.z));
        ivB[pb3] = make_int2(r4.w, __float_as_int(v4.w));
    } else if (j < nnz) {
        for (int k = j; k < nnz; k++) {
            int r = rows[k], c = cols[k];
            int v = __float_as_int(vals[k]);
            int pa = atomicAdd(workA + r, 1);
            ivA[pa] = make_int2(c, v);
            int pb = atomicAdd(workB + c, 1);
            ivB[pb] = make_int2(r, v);
        }
    }
}

// ---------------------------------------------------------------------------
// CSR SpMM, HALF-WARP per row (16 lanes x LDG.128 = 256B fp16 row),
// unroll-4 main loop + serial tail (known-good form).
//   if (out_h)   out_h[row] = acc_raw                       (fp16, scaled)
//   if (out_f)   out_f[row] = acc_raw * 1024                (fp32)
//   if (sum_out) sum_out[row] = sum_base[row]
//                 + 1024 * (acc_raw + add1h[row] + add2h[row])   (deferred sum)
// ---------------------------------------------------------------------------
__global__ __launch_bounds__(256)
void spmm_csr_h_kernel(const int* __restrict__ ptr, const int2* __restrict__ iv,
                       const uint4* __restrict__ xh,
                       float4* __restrict__ out_f, uint4* __restrict__ out_h,
                       const float4* __restrict__ sum_base,
                       const uint4* __restrict__ add1h, const uint4* __restrict__ add2h,
                       float4* __restrict__ sum_out, int n_rows)
{
    int row = blockIdx.x * 16 + (threadIdx.x >> 4);
    if (row >= n_rows) return;
    const int lane = threadIdx.x & 15;   // owns 8 halfs (one uint4)

    int e   = __ldg(ptr + row);
    int end = __ldg(ptr + row + 1);

    float4 a0 = make_float4(0.f, 0.f, 0.f, 0.f);
    float4 a1 = make_float4(0.f, 0.f, 0.f, 0.f);

    for (; e + 4 <= end; e += 4) {
        int2 p0 = __ldg(iv + e);
        int2 p1 = __ldg(iv + e + 1);
        int2 p2 = __ldg(iv + e + 2);
        int2 p3 = __ldg(iv + e + 3);
        uint4 r0 = __ldg(xh + (size_t)p0.x * 16 + lane);
        uint4 r1 = __ldg(xh + (size_t)p1.x * 16 + lane);
        uint4 r2 = __ldg(xh + (size_t)p2.x * 16 + lane);
        uint4 r3 = __ldg(xh + (size_t)p3.x * 16 + lane);
        float v0 = __int_as_float(p0.y), v1 = __int_as_float(p1.y);
        float v2 = __int_as_float(p2.y), v3 = __int_as_float(p3.y);
        float4 u;
        u = unpack_h4(r0.x, r0.y);
        a0.x += v0 * u.x; a0.y += v0 * u.y; a0.z += v0 * u.z; a0.w += v0 * u.w;
        u = unpack_h4(r0.z, r0.w);
        a1.x += v0 * u.x; a1.y += v0 * u.y; a1.z += v0 * u.z; a1.w += v0 * u.w;
        u = unpack_h4(r1.x, r1.y);
        a0.x += v1 * u.x; a0.y += v1 * u.y; a0.z += v1 * u.z; a0.w += v1 * u.w;
        u = unpack_h4(r1.z, r1.w);
        a1.x += v1 * u.x; a1.y += v1 * u.y; a1.z += v1 * u.z; a1.w += v1 * u.w;
        u = unpack_h4(r2.x, r2.y);
        a0.x += v2 * u.x; a0.y += v2 * u.y; a0.z += v2 * u.z; a0.w += v2 * u.w;
        u = unpack_h4(r2.z, r2.w);
        a1.x += v2 * u.x; a1.y += v2 * u.y; a1.z += v2 * u.z; a1.w += v2 * u.w;
        u = unpack_h4(r3.x, r3.y);
        a0.x += v3 * u.x; a0.y += v3 * u.y; a0.z += v3 * u.z; a0.w += v3 * u.w;
        u = unpack_h4(r3.z, r3.w);
        a1.x += v3 * u.x; a1.y += v3 * u.y; a1.z += v3 * u.z; a1.w += v3 * u.w;
    }
    for (; e < end; ++e) {
        int2 p = __ldg(iv + e);
        float v = __int_as_float(p.y);
        uint4 r = __ldg(xh + (size_t)p.x * 16 + lane);
        float4 u;
        u = unpack_h4(r.x, r.y);
        a0.x += v * u.x; a0.y += v * u.y; a0.z += v * u.z; a0.w += v * u.w;
        u = unpack_h4(r.z, r.w);
        a1.x += v * u.x; a1.y += v * u.y; a1.z += v * u.z; a1.w += v * u.w;
    }

    size_t o = (size_t)row * 16 + lane;
    if (out_h) {
        uint2 h0 = pack_h4(a0);
        uint2 h1 = pack_h4(a1);
        out_h[o] = make_uint4(h0.x, h0.y, h1.x, h1.y);
    }
    if (out_f) {
        out_f[2 * o]     = make_float4(a0.x * H_UNSCALE, a0.y * H_UNSCALE,
                                       a0.z * H_UNSCALE, a0.w * H_UNSCALE);
        out_f[2 * o + 1] = make_float4(a1.x * H_UNSCALE, a1.y * H_UNSCALE,
                                       a1.z * H_UNSCALE, a1.w * H_UNSCALE);
    }
    if (sum_out) {
        if (add1h) {   // deferred accumulation of earlier layers (scaled fp16)
            uint4 x1 = __ldg(add1h + o);
            uint4 x2 = __ldg(add2h + o);
            float4 u;
            u = unpack_h4(x1.x, x1.y);
            a0.x += u.x; a0.y += u.y; a0.z += u.z; a0.w += u.w;
            u = unpack_h4(x1.z, x1.w);
            a1.x += u.x; a1.y += u.y; a1.z += u.z; a1.w += u.w;
            u = unpack_h4(x2.x, x2.y);
            a0.x += u.x; a0.y += u.y; a0.z += u.z; a0.w += u.w;
            u = unpack_h4(x2.z, x2.w);
            a1.x += u.x; a1.y += u.y; a1.z += u.z; a1.w += u.w;
        }
        float4 b0 = __ldg(sum_base + 2 * o);
        float4 b1 = __ldg(sum_base + 2 * o + 1);
        b0.x += a0.x * H_UNSCALE; b0.y += a0.y * H_UNSCALE;
        b0.z += a0.z * H_UNSCALE; b0.w += a0.w * H_UNSCALE;
        b1.x += a1.x * H_UNSCALE; b1.y += a1.y * H_UNSCALE;
        b1.z += a1.z * H_UNSCALE; b1.w += a1.w * H_UNSCALE;
        sum_out[2 * o]     = b0;
        sum_out[2 * o + 1] = b1;
    }
}

// ---------------------------------------------------------------------------
// Fused gated dense layer with packed FFMA2:
//   msg = concat(a, a*g) @ W + b ;  msg_h = msg * 2^-10 (fp16)
//   if (ebase): edge_sum = ebase + msg + 1024*(m1h + m2h)   (deferred, last layer)
// Persistent 148 blocks; W (128KB) + X tile (64 rows, 64KB) in dynamic smem.
// ---------------------------------------------------------------------------
__global__ void gemm_gate_kernel(const float* __restrict__ node_msg,
                                 const uint2* __restrict__ group_h,  // scaled fp16 gate
                                 const float* __restrict__ W,        // [2*DIM][DIM]
                                 const float* __restrict__ bias,     // [DIM]
                                 uint2* __restrict__ msg_h,          // scaled fp16 out
                                 const float* __restrict__ ebase,
                                 const uint2* __restrict__ m1h, const uint2* __restrict__ m2h,
                                 float* __restrict__ edge_sum,
                                 int n_groups)
{
    extern __shared__ float sm[];
    float4* Wsv = (float4*)sm;                     // 2*DIM*DIM floats (128 KB)
    float4* Xsv = (float4*)(sm + 2 * DIM * DIM);   // 64 rows * 2*DIM floats (64 KB)

    {
        const float4* Wv = (const float4*)W;
        for (int i = threadIdx.x; i < 2 * DIM * DIM / 4; i += blockDim.x)
            Wsv[i] = Wv[i];
    }

    const int warp = threadIdx.x >> 5;
    const int lane = threadIdx.x & 31;
    const float4 bv = ((const float4*)bias)[lane];
    const unsigned long long b_lo = pack2(bv.x, bv.y);
    const unsigned long long b_hi = pack2(bv.z, bv.w);

    const float4* nm4 = (const float4*)node_msg;
    __syncthreads();

    for (int tile = blockIdx.x * 64; tile < n_groups; tile += gridDim.x * 64) {
        for (int i = threadIdx.x; i < 64 * 32; i += 256) {
            int rr = i >> 5;
            int kq = i & 31;
            int row = tile + rr;
            float4 a = make_float4(0.f, 0.f, 0.f, 0.f);
            float4 g = make_float4(0.f, 0.f, 0.f, 0.f);
            if (row < n_groups) {
                a = nm4[(size_t)row * 32 + kq];
                uint2 gr = __ldg(group_h + (size_t)row * 32 + kq);
                g = unpack_h4(gr.x, gr.y);
            }
            Xsv[rr * 64 + kq] = a;
            Xsv[rr * 64 + 32 + kq] =
                make_float4(a.x * g.x * H_UNSCALE, a.y * g.y * H_UNSCALE,
                            a.z * g.z * H_UNSCALE, a.w * g.w * H_UNSCALE);
        }
        __syncthreads();

        unsigned long long acc_lo[8], acc_hi[8];
        #pragma unroll
        for (int r = 0; r < 8; r++) { acc_lo[r] = b_lo; acc_hi[r] = b_hi; }

        const float4* Xr = Xsv + warp * 8 * 64;

        #pragma unroll 1
        for (int kq = 0; kq < 64; kq++) {
            float4 xr[8];
            #pragma unroll
            for (int r = 0; r < 8; r++) xr[r] = Xr[r * 64 + kq];

            #pragma unroll
            for (int j = 0; j < 4; j++) {
                float4 w = Wsv[(kq * 4 + j) * 32 + lane];
                unsigned long long w_lo = pack2(w.x, w.y);
                unsigned long long w_hi = pack2(w.z, w.w);
                #pragma unroll
                for (int r = 0; r < 8; r++) {
                    float xs = (j == 0) ? xr[r].x : (j == 1) ? xr[r].y
                             : (j == 2) ? xr[r].z : xr[r].w;
                    unsigned long long x2 = pack2(xs, xs);
                    ffma2(acc_lo[r], x2, w_lo);
                    ffma2(acc_hi[r], x2, w_hi);
                }
            }
        }

        int r0 = tile + warp * 8;
        #pragma unroll
        for (int r = 0; r < 8; r++) {
            int row = r0 + r;
            if (row < n_groups) {
                float2 lo = unpack2(acc_lo[r]);
                float2 hi = unpack2(acc_hi[r]);
                float4 v = make_float4(lo.x, lo.y, hi.x, hi.y);
                size_t oi = (size_t)row * 32 + lane;
                msg_h[oi] = pack_h4(make_float4(v.x * H_SCALE, v.y * H_SCALE,
                                                v.z * H_SCALE, v.w * H_SCALE));
                if (ebase) {   // last layer: deferred edge_sum
                    uint2 g1 = __ldg(m1h + oi);
                    uint2 g2 = __ldg(m2h + oi);
                    float4 u1 = unpack_h4(g1.x, g1.y);
                    float4 u2 = unpack_h4(g2.x, g2.y);
                    float4 e = __ldg((const float4*)ebase + oi);
                    e.x += v.x + (u1.x + u2.x) * H_UNSCALE;
                    e.y += v.y + (u1.y + u2.y) * H_UNSCALE;
                    e.z += v.z + (u1.z + u2.z) * H_UNSCALE;
                    e.w += v.w + (u1.w + u2.w) * H_UNSCALE;
                    ((float4*)edge_sum)[oi] = e;
                }
            }
        }
        __syncthreads();
    }
}

// ---------------------------------------------------------------------------
extern "C" void kernel_launch(void* const* d_in, const int* in_sizes, int n_in,
                              void* d_out, int out_size)
{
    const float* group_emb = (const float*)d_in[0];
    const float* user_emb  = (const float*)d_in[1];
    const int*   rows      = (const int*)d_in[2];
    const int*   cols      = (const int*)d_in[3];
    const float* vals      = (const float*)d_in[4];
    const float* Ws        = (const float*)d_in[5];
    const float* bs        = (const float*)d_in[6];

    const int n_groups = in_sizes[0] / DIM;
    const int n_users  = in_sizes[1] / DIM;
    const int nnz      = in_sizes[2];
    const int layers   = in_sizes[6] / DIM;   // 3

    float* node_sum = (float*)d_out;                          // [n_users, DIM]
    float* edge_sum = (float*)d_out + (size_t)n_users * DIM;  // [n_groups, DIM]

    float* node_msg;
    __half *userh_base, *msgh_base;
    int *build, *ptrA, *workA, *ptrB, *workB;
    int2 *ivA, *ivB;
    cudaGetSymbolAddress((void**)&node_msg, g_node_msg);
    cudaGetSymbolAddress((void**)&userh_base, g_userh);
    cudaGetSymbolAddress((void**)&msgh_base, g_msgh);
    cudaGetSymbolAddress((void**)&build, g_build);
    cudaGetSymbolAddress((void**)&ptrA,  g_ptrA);
    cudaGetSymbolAddress((void**)&workA, g_workA);
    cudaGetSymbolAddress((void**)&ivA,   g_ivA);
    cudaGetSymbolAddress((void**)&ptrB,  g_ptrB);
    cudaGetSymbolAddress((void**)&workB, g_workB);
    cudaGetSymbolAddress((void**)&ivB,   g_ivB);

    int* cntA = build;
    int* cntB = build + MAX_GROUPS;
    unsigned long long* flags = (unsigned long long*)(build + MAX_GROUPS + MAX_USERS);

    __half* uh[2] = { userh_base, userh_base + (size_t)MAX_USERS * DIM };
    __half* mh[3] = { msgh_base,
                      msgh_base + (size_t)MAX_GROUPS * DIM,
                      msgh_base + 2 * (size_t)MAX_GROUPS * DIM };

    // ---- zero counters + scan flags (one memset) ----
    cudaMemsetAsync(build, 0, ((size_t)MAX_GROUPS + n_users + 1024) * sizeof(int), 0);

    // ---- conversion + histogram merged ----
    {
        int n4u = n_users * DIM / 4;
        int n4g = n_groups * DIM / 4;
        int nconv = n4u + n4g;
        int nhist = (nnz + 3) / 4;
        int nthreads = (nconv > nhist) ? nconv : nhist;
        conv_hist_kernel<<<(nthreads + 255) / 256, 256>>>(
            (const float4*)user_emb, (uint2*)uh[0], n4u,      // conv user -> uh[0]
            (const float4*)group_emb, (uint2*)mh[2], n4g,     // conv group -> mh[2]
            rows, cols, cntA, cntB, nnz);
    }

    // ---- scan + scatter ----
    const int nbA = (n_groups + 1023) / 1024;
    const int nbB = (n_users + 1023) / 1024;
    scan_lookback_kernel<<<nbA + nbB, 1024>>>(cntA, ptrA + 1, workA, ptrA, n_groups, nbA,
                                              cntB, ptrB + 1, workB, ptrB, n_users, flags);
    {
        int nsc = (nnz + 3) / 4;
        scatter_kernel<<<(nsc + 255) / 256, 256>>>(rows, cols, vals,
                                                   workA, ivA, workB, ivB, nnz);
    }

    // ---- Layers (deferred output sums) ----
    const int smem_bytes = (2 * DIM * DIM + 64 * 2 * DIM) * sizeof(float);
    cudaFuncSetAttribute(gemm_gate_kernel,
                         cudaFuncAttributeMaxDynamicSharedMemorySize, smem_bytes);

    const int spmmA_blocks = (n_groups + 15) / 16;
    const int spmmB_blocks = (n_users + 15) / 16;

    // buffer schedule (layers=3):
    //   user gathers: L0: uh[0]=conv(user_emb), L1: uh[1]=u1, L2: uh[0]=u2
    //   gates:        L0: mh[2]=conv(group),    L1: mh[0]=m1, L2: mh[1]=m2
    //   msg outs:     L0->mh[0], L1->mh[1], L2->mh[2]
    for (int i = 0; i < layers; i++) {
        const bool last = (i == layers - 1);
        const __half* ucur = (i == 0) ? uh[0] : (i == 1) ? uh[1] : uh[0];
        const __half* gate = (i == 0) ? mh[2] : (i == 1) ? mh[0] : mh[1];
        __half* mout = (i == 0) ? mh[0] : (i == 1) ? mh[1] : mh[2];
        __half* uout = (i == 0) ? uh[1] : (i == 1) ? uh[0] : nullptr;

        // node_msg = H @ ucur
        spmm_csr_h_kernel<<<spmmA_blocks, 256>>>(ptrA, ivA, (const uint4*)ucur,
                                                 (float4*)node_msg, nullptr,
                                                 nullptr, nullptr, nullptr, nullptr,
                                                 n_groups);

        // msg; last layer also writes edge_sum = group_emb + m1 + m2 + m3
        gemm_gate_kernel<<<148, 256, smem_bytes>>>(
            node_msg, (const uint2*)gate,
            Ws + (size_t)i * 2 * DIM * DIM, bs + (size_t)i * DIM,
            (uint2*)mout,
            last ? group_emb : nullptr,
            last ? (const uint2*)mh[0] : nullptr,
            last ? (const uint2*)mh[1] : nullptr,
            edge_sum, n_groups);

        // u_{i+1} = H^T @ msg; last layer writes node_sum = user_emb + u1 + u2 + u3
        spmm_csr_h_kernel<<<spmmB_blocks, 256>>>(ptrB, ivB, (const uint4*)mout,
                                                 nullptr, (uint4*)uout,
                                                 last ? (const float4*)user_emb : nullptr,
                                                 last ? (const uint4*)uh[1] : nullptr,
                                                 last ? (const uint4*)uh[0] : nullptr,
                                                 last ? (float4*)node_sum : nullptr,
                                                 n_users);
    }
}